// round 14
// baseline (speedup 1.0000x reference)
#include <cuda_runtime.h>
#include <cuda_fp16.h>
#include <stdint.h>

// out = silu(LN2(silu(LN1(concat(nodes, aggr[comps])) @ W1 + b1)) @ W2 + b2)
// Plain fp16 HMMA GEMMs (fp32 accum). A and W each rounded to fp16 once;
// dropped residual terms RSS ~4.2e-4 < 1e-3. LN folded algebraically.
// R13 = R12 with CTA tile 128x256, 512 threads (16 warps, warp 32x64), 2-stage.

#define FDIM 512
#define KDIM 1024
#define NPAD 100096

#define BM 128
#define BN 256
#define NCHUNK 16

#define ATILE_BYTES (128 * 128)              // 16 KB
#define BTILE_BYTES (256 * 128)              // 32 KB
#define G_STAGE (ATILE_BYTES + BTILE_BYTES)  // 48 KB
#define G_SMEM (2 * G_STAGE)                 // 96 KB

// ---------------- device scratch (allocation-free rule) ----------------
__device__ __half g_A[(size_t)NPAD * 1024];      // fp16(x) concat
__device__ __half g_H[(size_t)NPAD * 1024];      // fp16(silu(.))
__device__ __half g_W1p[(size_t)KDIM * KDIM];    // [c][k] = fp16(g1*W1)
__device__ __half g_W2p[(size_t)FDIM * KDIM];    // [c][k] = fp16(g2*W2)
__device__ float g_gW1[KDIM], g_eW1[KDIM];
__device__ float g_gW2[FDIM], g_eW2[FDIM];
__device__ float g_mu1[NPAD], g_rs1[NPAD], g_mu2[NPAD], g_rs2[NPAD];
__device__ float g_rsum[NPAD], g_rsq[NPAD];

// ---------------- PTX helpers ----------------
__device__ __forceinline__ uint32_t smem_u32(const void* p) {
    uint32_t a;
    asm("{ .reg .u64 t; cvta.to.shared.u64 t, %1; cvt.u32.u64 %0, t; }" : "=r"(a) : "l"(p));
    return a;
}
__device__ __forceinline__ void cp16(uint32_t dst, const void* src) {
    asm volatile("cp.async.cg.shared.global [%0], [%1], 16;" :: "r"(dst), "l"(src));
}
#define SWZ(o) ((o) ^ (((o) >> 3) & 0x70))

__device__ __forceinline__ void ldsm4(uint32_t* r, uint32_t addr) {
    asm volatile("ldmatrix.sync.aligned.m8n8.x4.shared.b16 {%0,%1,%2,%3}, [%4];"
                 : "=r"(r[0]), "=r"(r[1]), "=r"(r[2]), "=r"(r[3]) : "r"(addr));
}
__device__ __forceinline__ void mma16816(float* c, const uint32_t* a, const uint32_t* b) {
    asm volatile(
        "mma.sync.aligned.m16n8k16.row.col.f32.f16.f16.f32 "
        "{%0,%1,%2,%3}, {%4,%5,%6,%7}, {%8,%9}, {%0,%1,%2,%3};"
        : "+f"(c[0]), "+f"(c[1]), "+f"(c[2]), "+f"(c[3])
        : "r"(a[0]), "r"(a[1]), "r"(a[2]), "r"(a[3]), "r"(b[0]), "r"(b[1]));
}

// ---------------- pack: Wp[c][k] = fp16(g[k]*W[k][c]) ----------------------
__global__ void __launch_bounds__(256) pack_kernel(const float* __restrict__ W,
    const float* __restrict__ g, __half* __restrict__ Wp, int C) {
    size_t total = (size_t)C * KDIM;
    for (size_t idx = (size_t)blockIdx.x * 256 + threadIdx.x; idx < total;
         idx += (size_t)gridDim.x * 256) {
        int c = (int)(idx / KDIM);
        int k = (int)(idx % KDIM);
        Wp[idx] = __float2half(g[k] * W[(size_t)k * C + c]);
    }
}

// gW[c] = sum_k g[k] W[k][c];  eW[c] = sum_k lnb[k] W[k][c] + bias[c]
__global__ void __launch_bounds__(256) gemv_kernel(const float* __restrict__ W,
    const float* __restrict__ g, const float* __restrict__ lnb,
    const float* __restrict__ bias, float* __restrict__ gW, float* __restrict__ eW, int C) {
    int c = blockIdx.x;
    float sg = 0.f, sb = 0.f;
    for (int k = threadIdx.x; k < KDIM; k += 256) {
        float w = W[(size_t)k * C + c];
        sg += g[k] * w; sb += lnb[k] * w;
    }
    __shared__ float ra[256], rb[256];
    ra[threadIdx.x] = sg; rb[threadIdx.x] = sb; __syncthreads();
    for (int o = 128; o > 0; o >>= 1) {
        if (threadIdx.x < o) { ra[threadIdx.x] += ra[threadIdx.x + o]; rb[threadIdx.x] += rb[threadIdx.x + o]; }
        __syncthreads();
    }
    if (threadIdx.x == 0) { gW[c] = ra[0]; eW[c] = rb[0] + bias[c]; }
}

// ---------------- stage 1: LN1 stats + fp16 round of concat(x) -------------
__global__ void __launch_bounds__(128) s1_kernel(
    const float* __restrict__ nodes, const float* __restrict__ aggr,
    const int* __restrict__ comps,
    __half* __restrict__ Aout, float* __restrict__ mu1, float* __restrict__ rs1,
    float* __restrict__ rsum, float* __restrict__ rsq, int n) {
    int row = blockIdx.x;
    if (row >= n) return;
    int t = threadIdx.x;
    const float4* p0 = (const float4*)(nodes + (size_t)row * FDIM);
    const float4* p1 = (const float4*)(aggr + (size_t)comps[row] * FDIM);
    float4 v0 = p0[t], v1 = p1[t];
    float s = v0.x + v0.y + v0.z + v0.w + v1.x + v1.y + v1.z + v1.w;
    float q = v0.x * v0.x + v0.y * v0.y + v0.z * v0.z + v0.w * v0.w
            + v1.x * v1.x + v1.y * v1.y + v1.z * v1.z + v1.w * v1.w;
#pragma unroll
    for (int o = 16; o > 0; o >>= 1) {
        s += __shfl_xor_sync(0xffffffffu, s, o);
        q += __shfl_xor_sync(0xffffffffu, q, o);
    }
    __shared__ float ss[4], qs[4];
    if ((t & 31) == 0) { ss[t >> 5] = s; qs[t >> 5] = q; }
    __syncthreads();
    if (t == 0) {
        s = ss[0] + ss[1] + ss[2] + ss[3];
        q = qs[0] + qs[1] + qs[2] + qs[3];
        float mu = s * (1.0f / 1024.0f);
        float var = q * (1.0f / 1024.0f) - mu * mu;
        mu1[row] = mu; rs1[row] = rsqrtf(var + 1e-5f);
        rsum[row] = 0.f; rsq[row] = 0.f;
    }
    __half2* base = (__half2*)(Aout + (size_t)row * 1024);
    base[2 * t + 0]   = __floats2half2_rn(v0.x, v0.y);
    base[2 * t + 1]   = __floats2half2_rn(v0.z, v0.w);
    base[256 + 2 * t] = __floats2half2_rn(v1.x, v1.y);
    base[257 + 2 * t] = __floats2half2_rn(v1.z, v1.w);
}

__global__ void __launch_bounds__(256) stat2_kernel(const float* __restrict__ rsum,
    const float* __restrict__ rsq, float* __restrict__ mu2, float* __restrict__ rs2, int n) {
    int i = blockIdx.x * 256 + threadIdx.x;
    if (i >= n) return;
    float mu = rsum[i] * (1.0f / 1024.0f);
    float var = rsq[i] * (1.0f / 1024.0f) - mu * mu;
    mu2[i] = mu; rs2[i] = rsqrtf(var + 1e-5f);
}

// ---------------- HMMA GEMM: CTA 128x256, 512 thr, warp 32x64, 2 stages ----
// LAYER==1: epilogue -> silu -> H (fp16) + LN2 partial sums (atomics)
// LAYER==2: epilogue -> silu -> out (fp32)
template <int LAYER>
__global__ void __launch_bounds__(512, 1) gemm_kernel(
    const __half* __restrict__ Ain, const __half* __restrict__ Bp,
    const float* __restrict__ mu, const float* __restrict__ rs,
    const float* __restrict__ gW, const float* __restrict__ eW,
    __half* __restrict__ Hout, float* __restrict__ outp,
    float* __restrict__ rsum, float* __restrict__ rsq, int n, int ncols)
{
    extern __shared__ char smem[];
    uint32_t sb = smem_u32(smem);
    const int tid  = threadIdx.x;
    const int wid  = tid >> 5;
    const int lane = tid & 31;
    const int wm = wid & 3, wn = wid >> 2;    // 4 row-warps x 4 col-warps
    const int row0 = blockIdx.y * BM;
    const int col0 = blockIdx.x * BN;

    float acc[2][8][4];
#pragma unroll
    for (int mt = 0; mt < 2; mt++)
#pragma unroll
        for (int nt = 0; nt < 8; nt++)
#pragma unroll
            for (int i = 0; i < 4; i++) acc[mt][nt][i] = 0.f;

    auto load_chunk = [&](int c) {
        int st = c & 1;
        uint32_t abase = sb + st * G_STAGE;
        uint32_t bbase = abase + ATILE_BYTES;
        int kcol = c << 6;
#pragma unroll
        for (int i = 0; i < 2; i++) {
            int v = tid + i * 512, r = v >> 3, cc = v & 7;
            int rg = row0 + r; if (rg >= n) rg = n - 1;
            cp16(abase + SWZ(r * 128 + cc * 16), Ain + (size_t)rg * 1024 + kcol + cc * 8);
        }
#pragma unroll
        for (int i = 0; i < 4; i++) {
            int v = tid + i * 512, r = v >> 3, cc = v & 7;
            cp16(bbase + SWZ(r * 128 + cc * 16), Bp + (size_t)(col0 + r) * KDIM + kcol + cc * 8);
        }
        asm volatile("cp.async.commit_group;" ::: "memory");
    };

    load_chunk(0);

    const int a_row = wm * 32 + (lane & 15);
    const int b_row = wn * 64 + (lane & 15);
    const int k8    = (lane >> 4) * 8;

    for (int c = 0; c < NCHUNK; c++) {
        asm volatile("cp.async.wait_group 0;" ::: "memory");
        __syncthreads();
        if (c + 1 < NCHUNK) load_chunk(c + 1);

        int st = c & 1;
        uint32_t abase = sb + st * G_STAGE;
        uint32_t bbase = abase + ATILE_BYTES;
#pragma unroll
        for (int ks = 0; ks < 4; ks++) {
            uint32_t a[2][4], b[8][2];
#pragma unroll
            for (int mt = 0; mt < 2; mt++)
                ldsm4(a[mt], abase + SWZ((a_row + mt * 16) * 128 + (ks * 16 + k8) * 2));
#pragma unroll
            for (int nt16 = 0; nt16 < 4; nt16++) {
                uint32_t r[4];
                ldsm4(r, bbase + SWZ((b_row + nt16 * 16) * 128 + (ks * 16 + k8) * 2));
                b[2 * nt16 + 0][0] = r[0]; b[2 * nt16 + 0][1] = r[2];
                b[2 * nt16 + 1][0] = r[1]; b[2 * nt16 + 1][1] = r[3];
            }
#pragma unroll
            for (int mt = 0; mt < 2; mt++)
#pragma unroll
                for (int nt = 0; nt < 8; nt++)
                    mma16816(acc[mt][nt], a[mt], b[nt]);
        }
        __syncthreads();
    }

    // ---- epilogue ----
    const int qid   = lane >> 2;
    const int qlane = lane & 3;

    float gwv[8][2], ewv[8][2];
#pragma unroll
    for (int nt = 0; nt < 8; nt++) {
        int colb = col0 + wn * 64 + nt * 8 + qlane * 2;
        gwv[nt][0] = __ldg(gW + colb); gwv[nt][1] = __ldg(gW + colb + 1);
        ewv[nt][0] = __ldg(eW + colb); ewv[nt][1] = __ldg(eW + colb + 1);
    }

#pragma unroll
    for (int mt = 0; mt < 2; mt++) {
#pragma unroll
        for (int half = 0; half < 2; half++) {
            int row = row0 + wm * 32 + mt * 16 + qid + half * 8;
            bool valid = row < n;
            int rc = valid ? row : 0;
            float m_mu = mu[rc], m_rs = rs[rc];
            float ssum = 0.f, sq = 0.f;
#pragma unroll
            for (int nt = 0; nt < 8; nt++) {
                float c0 = m_rs * (acc[mt][nt][half * 2 + 0] - m_mu * gwv[nt][0]) + ewv[nt][0];
                float c1 = m_rs * (acc[mt][nt][half * 2 + 1] - m_mu * gwv[nt][1]) + ewv[nt][1];
                float h0 = c0 / (1.f + __expf(-c0));
                float h1 = c1 / (1.f + __expf(-c1));
                int colb = col0 + wn * 64 + nt * 8 + qlane * 2;
                if (LAYER == 1) {
                    ssum += h0 + h1; sq += h0 * h0 + h1 * h1;
                    if (valid)
                        *(__half2*)(Hout + (size_t)row * 1024 + colb) = __floats2half2_rn(h0, h1);
                } else {
                    if (valid) {
                        float2 v; v.x = h0; v.y = h1;
                        *(float2*)(outp + (size_t)row * ncols + colb) = v;
                    }
                }
            }
            if (LAYER == 1) {
                ssum += __shfl_xor_sync(0xffffffffu, ssum, 1);
                ssum += __shfl_xor_sync(0xffffffffu, ssum, 2);
                sq   += __shfl_xor_sync(0xffffffffu, sq, 1);
                sq   += __shfl_xor_sync(0xffffffffu, sq, 2);
                if (qlane == 0 && valid) {
                    atomicAdd(&rsum[row], ssum);
                    atomicAdd(&rsq[row], sq);
                }
            }
        }
    }
}

// ---------------------------------------------------------------------------
extern "C" void kernel_launch(void* const* d_in, const int* in_sizes, int n_in,
                              void* d_out, int out_size) {
    const float* nodes      = (const float*)d_in[1];
    const int*   comps      = (const int*)  d_in[2];
    const float* aggr_nodes = (const float*)d_in[4];
    const float* ln1_g      = (const float*)d_in[6];
    const float* ln1_b      = (const float*)d_in[7];
    const float* W1         = (const float*)d_in[8];
    const float* b1         = (const float*)d_in[9];
    const float* ln2_g      = (const float*)d_in[10];
    const float* ln2_b      = (const float*)d_in[11];
    const float* W2         = (const float*)d_in[12];
    const float* b2         = (const float*)d_in[13];
    float*       out        = (float*)d_out;

    const int n = in_sizes[1] / FDIM;

    __half *A, *H, *W1p, *W2p;
    float *gW1, *eW1, *gW2, *eW2, *mu1, *rs1, *mu2, *rs2, *rsum, *rsq;
    cudaGetSymbolAddress((void**)&A,    g_A);
    cudaGetSymbolAddress((void**)&H,    g_H);
    cudaGetSymbolAddress((void**)&W1p,  g_W1p);
    cudaGetSymbolAddress((void**)&W2p,  g_W2p);
    cudaGetSymbolAddress((void**)&gW1,  g_gW1);
    cudaGetSymbolAddress((void**)&eW1,  g_eW1);
    cudaGetSymbolAddress((void**)&gW2,  g_gW2);
    cudaGetSymbolAddress((void**)&eW2,  g_eW2);
    cudaGetSymbolAddress((void**)&mu1,  g_mu1);
    cudaGetSymbolAddress((void**)&rs1,  g_rs1);
    cudaGetSymbolAddress((void**)&mu2,  g_mu2);
    cudaGetSymbolAddress((void**)&rs2,  g_rs2);
    cudaGetSymbolAddress((void**)&rsum, g_rsum);
    cudaGetSymbolAddress((void**)&rsq,  g_rsq);

    cudaFuncSetAttribute(gemm_kernel<1>, cudaFuncAttributeMaxDynamicSharedMemorySize, G_SMEM);
    cudaFuncSetAttribute(gemm_kernel<2>, cudaFuncAttributeMaxDynamicSharedMemorySize, G_SMEM);

    const int rtiles = (n + BM - 1) / BM;

    // precompute (deterministic, every call)
    pack_kernel<<<1024, 256>>>(W1, ln1_g, W1p, KDIM);
    pack_kernel<<<512, 256>>>(W2, ln2_g, W2p, FDIM);
    gemv_kernel<<<KDIM, 256>>>(W1, ln1_g, ln1_b, b1, gW1, eW1, KDIM);
    gemv_kernel<<<FDIM, 256>>>(W2, ln2_g, ln2_b, b2, gW2, eW2, FDIM);

    // stage 1: LN1 stats + fp16 round of concat(x)
    s1_kernel<<<n, 128>>>(nodes, aggr_nodes, comps, A, mu1, rs1, rsum, rsq, n);

    // GEMM1 (1-term): h (fp16) + LN2 partial sums
    gemm_kernel<1><<<dim3(KDIM / BN, rtiles), 512, G_SMEM>>>(
        A, W1p, mu1, rs1, gW1, eW1, H, nullptr, rsum, rsq, n, KDIM);

    // LN2 stats
    stat2_kernel<<<(n + 255) / 256, 256>>>(rsum, rsq, mu2, rs2, n);

    // GEMM2 (1-term) -> out
    gemm_kernel<2><<<dim3(FDIM / BN, rtiles), 512, G_SMEM>>>(
        H, W2p, mu2, rs2, gW2, eW2, nullptr, out, nullptr, nullptr, n, FDIM);
}

// round 15
// speedup vs baseline: 1.0882x; 1.0882x over previous
#include <cuda_runtime.h>
#include <cuda_fp16.h>
#include <stdint.h>

// out = silu(LN2(silu(LN1(concat(nodes, aggr[comps])) @ W1 + b1)) @ W2 + b2)
// Plain fp16 HMMA GEMMs (fp32 accum). A and W each rounded to fp16 once;
// dropped residual terms RSS ~4.2e-4 < 1e-3. LN folded algebraically.
// R14 = R12 (997us config: BM=BN=128, 256 thr, warp 32x64, 3-stage, 2 CTA/SM)
//       + coalesced transpose pack + stat2 folded into GEMM2 epilogue.

#define FDIM 512
#define KDIM 1024
#define NPAD 100096

#define BM 128
#define BN 128
#define NCHUNK 16

#define TILE_BYTES (128 * 128)
#define G_STAGE (2 * TILE_BYTES)     // [A 16K][B 16K]
#define G_SMEM (3 * G_STAGE)         // 96 KB, 2 CTAs/SM

// ---------------- device scratch (allocation-free rule) ----------------
__device__ __half g_A[(size_t)NPAD * 1024];      // fp16(x) concat
__device__ __half g_H[(size_t)NPAD * 1024];      // fp16(silu(.))
__device__ __half g_W1p[(size_t)KDIM * KDIM];    // [c][k] = fp16(g1*W1)
__device__ __half g_W2p[(size_t)FDIM * KDIM];    // [c][k] = fp16(g2*W2)
__device__ float g_gW1[KDIM], g_eW1[KDIM];
__device__ float g_gW2[FDIM], g_eW2[FDIM];
__device__ float g_mu1[NPAD], g_rs1[NPAD];
__device__ float g_rsum[NPAD], g_rsq[NPAD];

// ---------------- PTX helpers ----------------
__device__ __forceinline__ uint32_t smem_u32(const void* p) {
    uint32_t a;
    asm("{ .reg .u64 t; cvta.to.shared.u64 t, %1; cvt.u32.u64 %0, t; }" : "=r"(a) : "l"(p));
    return a;
}
__device__ __forceinline__ void cp16(uint32_t dst, const void* src) {
    asm volatile("cp.async.cg.shared.global [%0], [%1], 16;" :: "r"(dst), "l"(src));
}
#define SWZ(o) ((o) ^ (((o) >> 3) & 0x70))

__device__ __forceinline__ void ldsm4(uint32_t* r, uint32_t addr) {
    asm volatile("ldmatrix.sync.aligned.m8n8.x4.shared.b16 {%0,%1,%2,%3}, [%4];"
                 : "=r"(r[0]), "=r"(r[1]), "=r"(r[2]), "=r"(r[3]) : "r"(addr));
}
__device__ __forceinline__ void mma16816(float* c, const uint32_t* a, const uint32_t* b) {
    asm volatile(
        "mma.sync.aligned.m16n8k16.row.col.f32.f16.f16.f32 "
        "{%0,%1,%2,%3}, {%4,%5,%6,%7}, {%8,%9}, {%0,%1,%2,%3};"
        : "+f"(c[0]), "+f"(c[1]), "+f"(c[2]), "+f"(c[3])
        : "r"(a[0]), "r"(a[1]), "r"(a[2]), "r"(a[3]), "r"(b[0]), "r"(b[1]));
}

// ---------------- pack (transposed, coalesced both sides) ------------------
// Wp[c][k] = fp16(g[k] * W[k][c]); 32x32 tile through smem.
__global__ void __launch_bounds__(256) pack_kernel(const float* __restrict__ W,
    const float* __restrict__ g, __half* __restrict__ Wp, int C) {
    __shared__ float tile[32][33];
    const int tx = threadIdx.x & 31;
    const int ty = threadIdx.x >> 5;          // 0..7
    const int c0 = blockIdx.x * 32;
    const int k0 = blockIdx.y * 32;
#pragma unroll
    for (int i = 0; i < 4; i++) {
        int k = k0 + ty + i * 8;
        tile[ty + i * 8][tx] = g[k] * W[(size_t)k * C + c0 + tx];
    }
    __syncthreads();
#pragma unroll
    for (int i = 0; i < 4; i++) {
        int c = c0 + ty + i * 8;
        Wp[(size_t)c * KDIM + k0 + tx] = __float2half(tile[tx][ty + i * 8]);
    }
}

// gW[c] = sum_k g[k] W[k][c];  eW[c] = sum_k lnb[k] W[k][c] + bias[c]
__global__ void __launch_bounds__(256) gemv_kernel(const float* __restrict__ W,
    const float* __restrict__ g, const float* __restrict__ lnb,
    const float* __restrict__ bias, float* __restrict__ gW, float* __restrict__ eW, int C) {
    int c = blockIdx.x;
    float sg = 0.f, sb = 0.f;
    for (int k = threadIdx.x; k < KDIM; k += 256) {
        float w = W[(size_t)k * C + c];
        sg += g[k] * w; sb += lnb[k] * w;
    }
    __shared__ float ra[256], rb[256];
    ra[threadIdx.x] = sg; rb[threadIdx.x] = sb; __syncthreads();
    for (int o = 128; o > 0; o >>= 1) {
        if (threadIdx.x < o) { ra[threadIdx.x] += ra[threadIdx.x + o]; rb[threadIdx.x] += rb[threadIdx.x + o]; }
        __syncthreads();
    }
    if (threadIdx.x == 0) { gW[c] = ra[0]; eW[c] = rb[0] + bias[c]; }
}

// ---------------- stage 1: LN1 stats + fp16 round of concat(x) -------------
__global__ void __launch_bounds__(128) s1_kernel(
    const float* __restrict__ nodes, const float* __restrict__ aggr,
    const int* __restrict__ comps,
    __half* __restrict__ Aout, float* __restrict__ mu1, float* __restrict__ rs1,
    float* __restrict__ rsum, float* __restrict__ rsq, int n) {
    int row = blockIdx.x;
    if (row >= n) return;
    int t = threadIdx.x;
    const float4* p0 = (const float4*)(nodes + (size_t)row * FDIM);
    const float4* p1 = (const float4*)(aggr + (size_t)comps[row] * FDIM);
    float4 v0 = p0[t], v1 = p1[t];
    float s = v0.x + v0.y + v0.z + v0.w + v1.x + v1.y + v1.z + v1.w;
    float q = v0.x * v0.x + v0.y * v0.y + v0.z * v0.z + v0.w * v0.w
            + v1.x * v1.x + v1.y * v1.y + v1.z * v1.z + v1.w * v1.w;
#pragma unroll
    for (int o = 16; o > 0; o >>= 1) {
        s += __shfl_xor_sync(0xffffffffu, s, o);
        q += __shfl_xor_sync(0xffffffffu, q, o);
    }
    __shared__ float ss[4], qs[4];
    if ((t & 31) == 0) { ss[t >> 5] = s; qs[t >> 5] = q; }
    __syncthreads();
    if (t == 0) {
        s = ss[0] + ss[1] + ss[2] + ss[3];
        q = qs[0] + qs[1] + qs[2] + qs[3];
        float mu = s * (1.0f / 1024.0f);
        float var = q * (1.0f / 1024.0f) - mu * mu;
        mu1[row] = mu; rs1[row] = rsqrtf(var + 1e-5f);
        rsum[row] = 0.f; rsq[row] = 0.f;
    }
    __half2* base = (__half2*)(Aout + (size_t)row * 1024);
    base[2 * t + 0]   = __floats2half2_rn(v0.x, v0.y);
    base[2 * t + 1]   = __floats2half2_rn(v0.z, v0.w);
    base[256 + 2 * t] = __floats2half2_rn(v1.x, v1.y);
    base[257 + 2 * t] = __floats2half2_rn(v1.z, v1.w);
}

// ---------------- HMMA GEMM: 1-term, warp 32x64, 3 stages ------------------
// LAYER==1: mu/rs are precomputed LN1 stats; epilogue -> silu -> H (fp16) +
//           LN2 partial sums (atomics into rsum/rsq).
// LAYER==2: mu/rs pointers carry rsum/rsq; epilogue computes LN2 stats inline,
//           then silu -> out (fp32).
template <int LAYER>
__global__ void __launch_bounds__(256, 2) gemm_kernel(
    const __half* __restrict__ Ain, const __half* __restrict__ Bp,
    const float* __restrict__ mu, const float* __restrict__ rs,
    const float* __restrict__ gW, const float* __restrict__ eW,
    __half* __restrict__ Hout, float* __restrict__ outp,
    float* __restrict__ rsum, float* __restrict__ rsq, int n, int ncols)
{
    extern __shared__ char smem[];
    uint32_t sb = smem_u32(smem);
    const int tid  = threadIdx.x;
    const int wid  = tid >> 5;
    const int lane = tid & 31;
    const int wm = wid & 3, wn = wid >> 2;
    const int row0 = blockIdx.y * BM;
    const int col0 = blockIdx.x * BN;

    float acc[2][8][4];
#pragma unroll
    for (int mt = 0; mt < 2; mt++)
#pragma unroll
        for (int nt = 0; nt < 8; nt++)
#pragma unroll
            for (int i = 0; i < 4; i++) acc[mt][nt][i] = 0.f;

    auto load_chunk = [&](int c) {
        int st = c % 3;
        uint32_t abase = sb + st * G_STAGE;
        uint32_t bbase = abase + TILE_BYTES;
        int kcol = c << 6;
#pragma unroll
        for (int i = 0; i < 4; i++) {
            int v = tid + i * 256, r = v >> 3, cc = v & 7;
            int rg = row0 + r; if (rg >= n) rg = n - 1;
            cp16(abase + SWZ(r * 128 + cc * 16), Ain + (size_t)rg * 1024 + kcol + cc * 8);
        }
#pragma unroll
        for (int i = 0; i < 4; i++) {
            int v = tid + i * 256, r = v >> 3, cc = v & 7;
            cp16(bbase + SWZ(r * 128 + cc * 16), Bp + (size_t)(col0 + r) * KDIM + kcol + cc * 8);
        }
        asm volatile("cp.async.commit_group;" ::: "memory");
    };

    load_chunk(0);
    load_chunk(1);

    const int a_row = wm * 32 + (lane & 15);
    const int b_row = wn * 64 + (lane & 15);
    const int k8    = (lane >> 4) * 8;

    for (int c = 0; c < NCHUNK; c++) {
        if (c + 2 < NCHUNK) asm volatile("cp.async.wait_group 1;" ::: "memory");
        else                asm volatile("cp.async.wait_group 0;" ::: "memory");
        __syncthreads();
        if (c + 2 < NCHUNK) load_chunk(c + 2);

        uint32_t abase = sb + (c % 3) * G_STAGE;
        uint32_t bbase = abase + TILE_BYTES;
#pragma unroll
        for (int ks = 0; ks < 4; ks++) {
            uint32_t a[2][4], b[8][2];
#pragma unroll
            for (int mt = 0; mt < 2; mt++)
                ldsm4(a[mt], abase + SWZ((a_row + mt * 16) * 128 + (ks * 16 + k8) * 2));
#pragma unroll
            for (int nt16 = 0; nt16 < 4; nt16++) {
                uint32_t r[4];
                ldsm4(r, bbase + SWZ((b_row + nt16 * 16) * 128 + (ks * 16 + k8) * 2));
                b[2 * nt16 + 0][0] = r[0]; b[2 * nt16 + 0][1] = r[2];
                b[2 * nt16 + 1][0] = r[1]; b[2 * nt16 + 1][1] = r[3];
            }
#pragma unroll
            for (int mt = 0; mt < 2; mt++)
#pragma unroll
                for (int nt = 0; nt < 8; nt++)
                    mma16816(acc[mt][nt], a[mt], b[nt]);
        }
        __syncthreads();
    }

    // ---- epilogue ----
    const int qid   = lane >> 2;
    const int qlane = lane & 3;

    float gwv[8][2], ewv[8][2];
#pragma unroll
    for (int nt = 0; nt < 8; nt++) {
        int colb = col0 + wn * 64 + nt * 8 + qlane * 2;
        gwv[nt][0] = __ldg(gW + colb); gwv[nt][1] = __ldg(gW + colb + 1);
        ewv[nt][0] = __ldg(eW + colb); ewv[nt][1] = __ldg(eW + colb + 1);
    }

#pragma unroll
    for (int mt = 0; mt < 2; mt++) {
#pragma unroll
        for (int half = 0; half < 2; half++) {
            int row = row0 + wm * 32 + mt * 16 + qid + half * 8;
            bool valid = row < n;
            int rc = valid ? row : 0;
            float m_mu, m_rs;
            if (LAYER == 1) {
                m_mu = mu[rc]; m_rs = rs[rc];
            } else {
                // inline LN2 stats from accumulated row sums
                m_mu = mu[rc] * (1.0f / 1024.0f);
                float var = rs[rc] * (1.0f / 1024.0f) - m_mu * m_mu;
                m_rs = rsqrtf(var + 1e-5f);
            }
            float ssum = 0.f, sq = 0.f;
#pragma unroll
            for (int nt = 0; nt < 8; nt++) {
                float c0 = m_rs * (acc[mt][nt][half * 2 + 0] - m_mu * gwv[nt][0]) + ewv[nt][0];
                float c1 = m_rs * (acc[mt][nt][half * 2 + 1] - m_mu * gwv[nt][1]) + ewv[nt][1];
                float h0 = c0 / (1.f + __expf(-c0));
                float h1 = c1 / (1.f + __expf(-c1));
                int colb = col0 + wn * 64 + nt * 8 + qlane * 2;
                if (LAYER == 1) {
                    ssum += h0 + h1; sq += h0 * h0 + h1 * h1;
                    if (valid)
                        *(__half2*)(Hout + (size_t)row * 1024 + colb) = __floats2half2_rn(h0, h1);
                } else {
                    if (valid) {
                        float2 v; v.x = h0; v.y = h1;
                        *(float2*)(outp + (size_t)row * ncols + colb) = v;
                    }
                }
            }
            if (LAYER == 1) {
                ssum += __shfl_xor_sync(0xffffffffu, ssum, 1);
                ssum += __shfl_xor_sync(0xffffffffu, ssum, 2);
                sq   += __shfl_xor_sync(0xffffffffu, sq, 1);
                sq   += __shfl_xor_sync(0xffffffffu, sq, 2);
                if (qlane == 0 && valid) {
                    atomicAdd(&rsum[row], ssum);
                    atomicAdd(&rsq[row], sq);
                }
            }
        }
    }
}

// ---------------------------------------------------------------------------
extern "C" void kernel_launch(void* const* d_in, const int* in_sizes, int n_in,
                              void* d_out, int out_size) {
    const float* nodes      = (const float*)d_in[1];
    const int*   comps      = (const int*)  d_in[2];
    const float* aggr_nodes = (const float*)d_in[4];
    const float* ln1_g      = (const float*)d_in[6];
    const float* ln1_b      = (const float*)d_in[7];
    const float* W1         = (const float*)d_in[8];
    const float* b1         = (const float*)d_in[9];
    const float* ln2_g      = (const float*)d_in[10];
    const float* ln2_b      = (const float*)d_in[11];
    const float* W2         = (const float*)d_in[12];
    const float* b2         = (const float*)d_in[13];
    float*       out        = (float*)d_out;

    const int n = in_sizes[1] / FDIM;

    __half *A, *H, *W1p, *W2p;
    float *gW1, *eW1, *gW2, *eW2, *mu1, *rs1, *rsum, *rsq;
    cudaGetSymbolAddress((void**)&A,    g_A);
    cudaGetSymbolAddress((void**)&H,    g_H);
    cudaGetSymbolAddress((void**)&W1p,  g_W1p);
    cudaGetSymbolAddress((void**)&W2p,  g_W2p);
    cudaGetSymbolAddress((void**)&gW1,  g_gW1);
    cudaGetSymbolAddress((void**)&eW1,  g_eW1);
    cudaGetSymbolAddress((void**)&gW2,  g_gW2);
    cudaGetSymbolAddress((void**)&eW2,  g_eW2);
    cudaGetSymbolAddress((void**)&mu1,  g_mu1);
    cudaGetSymbolAddress((void**)&rs1,  g_rs1);
    cudaGetSymbolAddress((void**)&rsum, g_rsum);
    cudaGetSymbolAddress((void**)&rsq,  g_rsq);

    cudaFuncSetAttribute(gemm_kernel<1>, cudaFuncAttributeMaxDynamicSharedMemorySize, G_SMEM);
    cudaFuncSetAttribute(gemm_kernel<2>, cudaFuncAttributeMaxDynamicSharedMemorySize, G_SMEM);

    const int rtiles = (n + BM - 1) / BM;

    // precompute (deterministic, every call)
    pack_kernel<<<dim3(KDIM / 32, KDIM / 32), 256>>>(W1, ln1_g, W1p, KDIM);
    pack_kernel<<<dim3(FDIM / 32, KDIM / 32), 256>>>(W2, ln2_g, W2p, FDIM);
    gemv_kernel<<<KDIM, 256>>>(W1, ln1_g, ln1_b, b1, gW1, eW1, KDIM);
    gemv_kernel<<<FDIM, 256>>>(W2, ln2_g, ln2_b, b2, gW2, eW2, FDIM);

    // stage 1: LN1 stats + fp16 round of concat(x)
    s1_kernel<<<n, 128>>>(nodes, aggr_nodes, comps, A, mu1, rs1, rsum, rsq, n);

    // GEMM1 (1-term): h (fp16) + LN2 partial sums
    gemm_kernel<1><<<dim3(KDIM / BN, rtiles), 256, G_SMEM>>>(
        A, W1p, mu1, rs1, gW1, eW1, H, nullptr, rsum, rsq, n, KDIM);

    // GEMM2 (1-term, LN2 stats inline from rsum/rsq) -> out
    gemm_kernel<2><<<dim3(FDIM / BN, rtiles), 256, G_SMEM>>>(
        H, W2p, rsum, rsq, gW2, eW2, nullptr, out, nullptr, nullptr, n, FDIM);
}

// round 16
// speedup vs baseline: 1.1060x; 1.0163x over previous
#include <cuda_runtime.h>
#include <cuda_fp16.h>
#include <stdint.h>

// out = silu(LN2(silu(LN1(concat(nodes, aggr[comps])) @ W1 + b1)) @ W2 + b2)
// Plain fp16 HMMA GEMMs (fp32 accum). A and W each rounded to fp16 once;
// dropped residual terms RSS ~4.2e-4 < 1e-3. LN folded algebraically.
// R15 = R14 + warp-per-row s1 (12.5K blocks) + redundant mainloop barrier removed.

#define FDIM 512
#define KDIM 1024
#define NPAD 100096

#define BM 128
#define BN 128
#define NCHUNK 16

#define TILE_BYTES (128 * 128)
#define G_STAGE (2 * TILE_BYTES)     // [A 16K][B 16K]
#define G_SMEM (3 * G_STAGE)         // 96 KB, 2 CTAs/SM

// ---------------- device scratch (allocation-free rule) ----------------
__device__ __half g_A[(size_t)NPAD * 1024];      // fp16(x) concat
__device__ __half g_H[(size_t)NPAD * 1024];      // fp16(silu(.))
__device__ __half g_W1p[(size_t)KDIM * KDIM];    // [c][k] = fp16(g1*W1)
__device__ __half g_W2p[(size_t)FDIM * KDIM];    // [c][k] = fp16(g2*W2)
__device__ float g_gW1[KDIM], g_eW1[KDIM];
__device__ float g_gW2[FDIM], g_eW2[FDIM];
__device__ float g_mu1[NPAD], g_rs1[NPAD];
__device__ float g_rsum[NPAD], g_rsq[NPAD];

// ---------------- PTX helpers ----------------
__device__ __forceinline__ uint32_t smem_u32(const void* p) {
    uint32_t a;
    asm("{ .reg .u64 t; cvta.to.shared.u64 t, %1; cvt.u32.u64 %0, t; }" : "=r"(a) : "l"(p));
    return a;
}
__device__ __forceinline__ void cp16(uint32_t dst, const void* src) {
    asm volatile("cp.async.cg.shared.global [%0], [%1], 16;" :: "r"(dst), "l"(src));
}
#define SWZ(o) ((o) ^ (((o) >> 3) & 0x70))

__device__ __forceinline__ void ldsm4(uint32_t* r, uint32_t addr) {
    asm volatile("ldmatrix.sync.aligned.m8n8.x4.shared.b16 {%0,%1,%2,%3}, [%4];"
                 : "=r"(r[0]), "=r"(r[1]), "=r"(r[2]), "=r"(r[3]) : "r"(addr));
}
__device__ __forceinline__ void mma16816(float* c, const uint32_t* a, const uint32_t* b) {
    asm volatile(
        "mma.sync.aligned.m16n8k16.row.col.f32.f16.f16.f32 "
        "{%0,%1,%2,%3}, {%4,%5,%6,%7}, {%8,%9}, {%0,%1,%2,%3};"
        : "+f"(c[0]), "+f"(c[1]), "+f"(c[2]), "+f"(c[3])
        : "r"(a[0]), "r"(a[1]), "r"(a[2]), "r"(a[3]), "r"(b[0]), "r"(b[1]));
}

// ---------------- pack (transposed, coalesced both sides) ------------------
// Wp[c][k] = fp16(g[k] * W[k][c]); 32x32 tile through smem.
__global__ void __launch_bounds__(256) pack_kernel(const float* __restrict__ W,
    const float* __restrict__ g, __half* __restrict__ Wp, int C) {
    __shared__ float tile[32][33];
    const int tx = threadIdx.x & 31;
    const int ty = threadIdx.x >> 5;          // 0..7
    const int c0 = blockIdx.x * 32;
    const int k0 = blockIdx.y * 32;
#pragma unroll
    for (int i = 0; i < 4; i++) {
        int k = k0 + ty + i * 8;
        tile[ty + i * 8][tx] = g[k] * W[(size_t)k * C + c0 + tx];
    }
    __syncthreads();
#pragma unroll
    for (int i = 0; i < 4; i++) {
        int c = c0 + ty + i * 8;
        Wp[(size_t)c * KDIM + k0 + tx] = __float2half(tile[tx][ty + i * 8]);
    }
}

// gW[c] = sum_k g[k] W[k][c];  eW[c] = sum_k lnb[k] W[k][c] + bias[c]
__global__ void __launch_bounds__(256) gemv_kernel(const float* __restrict__ W,
    const float* __restrict__ g, const float* __restrict__ lnb,
    const float* __restrict__ bias, float* __restrict__ gW, float* __restrict__ eW, int C) {
    int c = blockIdx.x;
    float sg = 0.f, sb = 0.f;
    for (int k = threadIdx.x; k < KDIM; k += 256) {
        float w = W[(size_t)k * C + c];
        sg += g[k] * w; sb += lnb[k] * w;
    }
    __shared__ float ra[256], rb[256];
    ra[threadIdx.x] = sg; rb[threadIdx.x] = sb; __syncthreads();
    for (int o = 128; o > 0; o >>= 1) {
        if (threadIdx.x < o) { ra[threadIdx.x] += ra[threadIdx.x + o]; rb[threadIdx.x] += rb[threadIdx.x + o]; }
        __syncthreads();
    }
    if (threadIdx.x == 0) { gW[c] = ra[0]; eW[c] = rb[0] + bias[c]; }
}

// ---------------- stage 1: LN1 stats + fp16 round, one warp per row --------
__global__ void __launch_bounds__(256) s1_kernel(
    const float* __restrict__ nodes, const float* __restrict__ aggr,
    const int* __restrict__ comps,
    __half* __restrict__ Aout, float* __restrict__ mu1, float* __restrict__ rs1,
    float* __restrict__ rsum, float* __restrict__ rsq, int n) {
    const int lane = threadIdx.x & 31;
    const int row  = blockIdx.x * 8 + (threadIdx.x >> 5);
    if (row >= n) return;
    const float4* p0 = (const float4*)(nodes + (size_t)row * FDIM);
    const float4* p1 = (const float4*)(aggr + (size_t)comps[row] * FDIM);
    float4 v0[4], v1[4];
#pragma unroll
    for (int i = 0; i < 4; i++) { v0[i] = p0[lane + 32 * i]; v1[i] = p1[lane + 32 * i]; }
    float s = 0.f, q = 0.f;
#pragma unroll
    for (int i = 0; i < 4; i++) {
        s += v0[i].x + v0[i].y + v0[i].z + v0[i].w + v1[i].x + v1[i].y + v1[i].z + v1[i].w;
        q += v0[i].x * v0[i].x + v0[i].y * v0[i].y + v0[i].z * v0[i].z + v0[i].w * v0[i].w
           + v1[i].x * v1[i].x + v1[i].y * v1[i].y + v1[i].z * v1[i].z + v1[i].w * v1[i].w;
    }
#pragma unroll
    for (int o = 16; o > 0; o >>= 1) {
        s += __shfl_xor_sync(0xffffffffu, s, o);
        q += __shfl_xor_sync(0xffffffffu, q, o);
    }
    if (lane == 0) {
        float mu = s * (1.0f / 1024.0f);
        float var = q * (1.0f / 1024.0f) - mu * mu;
        mu1[row] = mu; rs1[row] = rsqrtf(var + 1e-5f);
        rsum[row] = 0.f; rsq[row] = 0.f;
    }
    __half2* base = (__half2*)(Aout + (size_t)row * 1024);
#pragma unroll
    for (int i = 0; i < 4; i++) {
        int f = lane + 32 * i;
        base[2 * f + 0]       = __floats2half2_rn(v0[i].x, v0[i].y);
        base[2 * f + 1]       = __floats2half2_rn(v0[i].z, v0[i].w);
        base[256 + 2 * f + 0] = __floats2half2_rn(v1[i].x, v1[i].y);
        base[256 + 2 * f + 1] = __floats2half2_rn(v1[i].z, v1[i].w);
    }
}

// ---------------- HMMA GEMM: 1-term, warp 32x64, 3 stages ------------------
// LAYER==1: mu/rs are precomputed LN1 stats; epilogue -> silu -> H (fp16) +
//           LN2 partial sums (atomics into rsum/rsq).
// LAYER==2: mu/rs pointers carry rsum/rsq; epilogue computes LN2 stats inline,
//           then silu -> out (fp32).
template <int LAYER>
__global__ void __launch_bounds__(256, 2) gemm_kernel(
    const __half* __restrict__ Ain, const __half* __restrict__ Bp,
    const float* __restrict__ mu, const float* __restrict__ rs,
    const float* __restrict__ gW, const float* __restrict__ eW,
    __half* __restrict__ Hout, float* __restrict__ outp,
    float* __restrict__ rsum, float* __restrict__ rsq, int n, int ncols)
{
    extern __shared__ char smem[];
    uint32_t sb = smem_u32(smem);
    const int tid  = threadIdx.x;
    const int wid  = tid >> 5;
    const int lane = tid & 31;
    const int wm = wid & 3, wn = wid >> 2;
    const int row0 = blockIdx.y * BM;
    const int col0 = blockIdx.x * BN;

    float acc[2][8][4];
#pragma unroll
    for (int mt = 0; mt < 2; mt++)
#pragma unroll
        for (int nt = 0; nt < 8; nt++)
#pragma unroll
            for (int i = 0; i < 4; i++) acc[mt][nt][i] = 0.f;

    auto load_chunk = [&](int c) {
        int st = c % 3;
        uint32_t abase = sb + st * G_STAGE;
        uint32_t bbase = abase + TILE_BYTES;
        int kcol = c << 6;
#pragma unroll
        for (int i = 0; i < 4; i++) {
            int v = tid + i * 256, r = v >> 3, cc = v & 7;
            int rg = row0 + r; if (rg >= n) rg = n - 1;
            cp16(abase + SWZ(r * 128 + cc * 16), Ain + (size_t)rg * 1024 + kcol + cc * 8);
        }
#pragma unroll
        for (int i = 0; i < 4; i++) {
            int v = tid + i * 256, r = v >> 3, cc = v & 7;
            cp16(bbase + SWZ(r * 128 + cc * 16), Bp + (size_t)(col0 + r) * KDIM + kcol + cc * 8);
        }
        asm volatile("cp.async.commit_group;" ::: "memory");
    };

    load_chunk(0);
    load_chunk(1);

    const int a_row = wm * 32 + (lane & 15);
    const int b_row = wn * 64 + (lane & 15);
    const int k8    = (lane >> 4) * 8;

    for (int c = 0; c < NCHUNK; c++) {
        if (c + 2 < NCHUNK) asm volatile("cp.async.wait_group 1;" ::: "memory");
        else                asm volatile("cp.async.wait_group 0;" ::: "memory");
        __syncthreads();
        // This barrier also publishes compute-done for stage (c-1)%3 == (c+2)%3,
        // so the load below is safe and the trailing barrier is unnecessary.
        if (c + 2 < NCHUNK) load_chunk(c + 2);

        uint32_t abase = sb + (c % 3) * G_STAGE;
        uint32_t bbase = abase + TILE_BYTES;
#pragma unroll
        for (int ks = 0; ks < 4; ks++) {
            uint32_t a[2][4], b[8][2];
#pragma unroll
            for (int mt = 0; mt < 2; mt++)
                ldsm4(a[mt], abase + SWZ((a_row + mt * 16) * 128 + (ks * 16 + k8) * 2));
#pragma unroll
            for (int nt16 = 0; nt16 < 4; nt16++) {
                uint32_t r[4];
                ldsm4(r, bbase + SWZ((b_row + nt16 * 16) * 128 + (ks * 16 + k8) * 2));
                b[2 * nt16 + 0][0] = r[0]; b[2 * nt16 + 0][1] = r[2];
                b[2 * nt16 + 1][0] = r[1]; b[2 * nt16 + 1][1] = r[3];
            }
#pragma unroll
            for (int mt = 0; mt < 2; mt++)
#pragma unroll
                for (int nt = 0; nt < 8; nt++)
                    mma16816(acc[mt][nt], a[mt], b[nt]);
        }
    }

    // ---- epilogue ----
    const int qid   = lane >> 2;
    const int qlane = lane & 3;

    float gwv[8][2], ewv[8][2];
#pragma unroll
    for (int nt = 0; nt < 8; nt++) {
        int colb = col0 + wn * 64 + nt * 8 + qlane * 2;
        gwv[nt][0] = __ldg(gW + colb); gwv[nt][1] = __ldg(gW + colb + 1);
        ewv[nt][0] = __ldg(eW + colb); ewv[nt][1] = __ldg(eW + colb + 1);
    }

#pragma unroll
    for (int mt = 0; mt < 2; mt++) {
#pragma unroll
        for (int half = 0; half < 2; half++) {
            int row = row0 + wm * 32 + mt * 16 + qid + half * 8;
            bool valid = row < n;
            int rc = valid ? row : 0;
            float m_mu, m_rs;
            if (LAYER == 1) {
                m_mu = mu[rc]; m_rs = rs[rc];
            } else {
                // inline LN2 stats from accumulated row sums
                m_mu = mu[rc] * (1.0f / 1024.0f);
                float var = rs[rc] * (1.0f / 1024.0f) - m_mu * m_mu;
                m_rs = rsqrtf(var + 1e-5f);
            }
            float ssum = 0.f, sq = 0.f;
#pragma unroll
            for (int nt = 0; nt < 8; nt++) {
                float c0 = m_rs * (acc[mt][nt][half * 2 + 0] - m_mu * gwv[nt][0]) + ewv[nt][0];
                float c1 = m_rs * (acc[mt][nt][half * 2 + 1] - m_mu * gwv[nt][1]) + ewv[nt][1];
                float h0 = c0 / (1.f + __expf(-c0));
                float h1 = c1 / (1.f + __expf(-c1));
                int colb = col0 + wn * 64 + nt * 8 + qlane * 2;
                if (LAYER == 1) {
                    ssum += h0 + h1; sq += h0 * h0 + h1 * h1;
                    if (valid)
                        *(__half2*)(Hout + (size_t)row * 1024 + colb) = __floats2half2_rn(h0, h1);
                } else {
                    if (valid) {
                        float2 v; v.x = h0; v.y = h1;
                        *(float2*)(outp + (size_t)row * ncols + colb) = v;
                    }
                }
            }
            if (LAYER == 1) {
                ssum += __shfl_xor_sync(0xffffffffu, ssum, 1);
                ssum += __shfl_xor_sync(0xffffffffu, ssum, 2);
                sq   += __shfl_xor_sync(0xffffffffu, sq, 1);
                sq   += __shfl_xor_sync(0xffffffffu, sq, 2);
                if (qlane == 0 && valid) {
                    atomicAdd(&rsum[row], ssum);
                    atomicAdd(&rsq[row], sq);
                }
            }
        }
    }
}

// ---------------------------------------------------------------------------
extern "C" void kernel_launch(void* const* d_in, const int* in_sizes, int n_in,
                              void* d_out, int out_size) {
    const float* nodes      = (const float*)d_in[1];
    const int*   comps      = (const int*)  d_in[2];
    const float* aggr_nodes = (const float*)d_in[4];
    const float* ln1_g      = (const float*)d_in[6];
    const float* ln1_b      = (const float*)d_in[7];
    const float* W1         = (const float*)d_in[8];
    const float* b1         = (const float*)d_in[9];
    const float* ln2_g      = (const float*)d_in[10];
    const float* ln2_b      = (const float*)d_in[11];
    const float* W2         = (const float*)d_in[12];
    const float* b2         = (const float*)d_in[13];
    float*       out        = (float*)d_out;

    const int n = in_sizes[1] / FDIM;

    __half *A, *H, *W1p, *W2p;
    float *gW1, *eW1, *gW2, *eW2, *mu1, *rs1, *rsum, *rsq;
    cudaGetSymbolAddress((void**)&A,    g_A);
    cudaGetSymbolAddress((void**)&H,    g_H);
    cudaGetSymbolAddress((void**)&W1p,  g_W1p);
    cudaGetSymbolAddress((void**)&W2p,  g_W2p);
    cudaGetSymbolAddress((void**)&gW1,  g_gW1);
    cudaGetSymbolAddress((void**)&eW1,  g_eW1);
    cudaGetSymbolAddress((void**)&gW2,  g_gW2);
    cudaGetSymbolAddress((void**)&eW2,  g_eW2);
    cudaGetSymbolAddress((void**)&mu1,  g_mu1);
    cudaGetSymbolAddress((void**)&rs1,  g_rs1);
    cudaGetSymbolAddress((void**)&rsum, g_rsum);
    cudaGetSymbolAddress((void**)&rsq,  g_rsq);

    cudaFuncSetAttribute(gemm_kernel<1>, cudaFuncAttributeMaxDynamicSharedMemorySize, G_SMEM);
    cudaFuncSetAttribute(gemm_kernel<2>, cudaFuncAttributeMaxDynamicSharedMemorySize, G_SMEM);

    const int rtiles = (n + BM - 1) / BM;

    // precompute (deterministic, every call)
    pack_kernel<<<dim3(KDIM / 32, KDIM / 32), 256>>>(W1, ln1_g, W1p, KDIM);
    pack_kernel<<<dim3(FDIM / 32, KDIM / 32), 256>>>(W2, ln2_g, W2p, FDIM);
    gemv_kernel<<<KDIM, 256>>>(W1, ln1_g, ln1_b, b1, gW1, eW1, KDIM);
    gemv_kernel<<<FDIM, 256>>>(W2, ln2_g, ln2_b, b2, gW2, eW2, FDIM);

    // stage 1: LN1 stats + fp16 round of concat(x), one warp per row
    s1_kernel<<<(n + 7) / 8, 256>>>(nodes, aggr_nodes, comps, A, mu1, rs1, rsum, rsq, n);

    // GEMM1 (1-term): h (fp16) + LN2 partial sums
    gemm_kernel<1><<<dim3(KDIM / BN, rtiles), 256, G_SMEM>>>(
        A, W1p, mu1, rs1, gW1, eW1, H, nullptr, rsum, rsq, n, KDIM);

    // GEMM2 (1-term, LN2 stats inline from rsum/rsq) -> out
    gemm_kernel<2><<<dim3(FDIM / BN, rtiles), 256, G_SMEM>>>(
        H, W2p, rsum, rsq, gW2, eW2, nullptr, out, nullptr, nullptr, n, FDIM);
}

// round 17
// speedup vs baseline: 1.1095x; 1.0032x over previous
#include <cuda_runtime.h>
#include <cuda_fp16.h>
#include <stdint.h>

// out = silu(LN2(silu(LN1(concat(nodes, aggr[comps])) @ W1 + b1)) @ W2 + b2)
// Plain fp16 HMMA GEMMs (fp32 accum). A and W each rounded to fp16 once;
// dropped residual terms RSS ~4.2e-4 < 1e-3. LN folded algebraically.
// R16 = R15 + gemv fused into pack (per-tile warp reductions + atomicAdd),
//       single W read, 2 fewer launches.

#define FDIM 512
#define KDIM 1024
#define NPAD 100096

#define BM 128
#define BN 128
#define NCHUNK 16

#define TILE_BYTES (128 * 128)
#define G_STAGE (2 * TILE_BYTES)     // [A 16K][B 16K]
#define G_SMEM (3 * G_STAGE)         // 96 KB, 2 CTAs/SM

// ---------------- device scratch (allocation-free rule) ----------------
__device__ __half g_A[(size_t)NPAD * 1024];      // fp16(x) concat
__device__ __half g_H[(size_t)NPAD * 1024];      // fp16(silu(.))
__device__ __half g_W1p[(size_t)KDIM * KDIM];    // [c][k] = fp16(g1*W1)
__device__ __half g_W2p[(size_t)FDIM * KDIM];    // [c][k] = fp16(g2*W2)
__device__ float g_gW1[KDIM], g_eW1[KDIM];
__device__ float g_gW2[FDIM], g_eW2[FDIM];
__device__ float g_mu1[NPAD], g_rs1[NPAD];
__device__ float g_rsum[NPAD], g_rsq[NPAD];

// ---------------- PTX helpers ----------------
__device__ __forceinline__ uint32_t smem_u32(const void* p) {
    uint32_t a;
    asm("{ .reg .u64 t; cvta.to.shared.u64 t, %1; cvt.u32.u64 %0, t; }" : "=r"(a) : "l"(p));
    return a;
}
__device__ __forceinline__ void cp16(uint32_t dst, const void* src) {
    asm volatile("cp.async.cg.shared.global [%0], [%1], 16;" :: "r"(dst), "l"(src));
}
#define SWZ(o) ((o) ^ (((o) >> 3) & 0x70))

__device__ __forceinline__ void ldsm4(uint32_t* r, uint32_t addr) {
    asm volatile("ldmatrix.sync.aligned.m8n8.x4.shared.b16 {%0,%1,%2,%3}, [%4];"
                 : "=r"(r[0]), "=r"(r[1]), "=r"(r[2]), "=r"(r[3]) : "r"(addr));
}
__device__ __forceinline__ void mma16816(float* c, const uint32_t* a, const uint32_t* b) {
    asm volatile(
        "mma.sync.aligned.m16n8k16.row.col.f32.f16.f16.f32 "
        "{%0,%1,%2,%3}, {%4,%5,%6,%7}, {%8,%9}, {%0,%1,%2,%3};"
        : "+f"(c[0]), "+f"(c[1]), "+f"(c[2]), "+f"(c[3])
        : "r"(a[0]), "r"(a[1]), "r"(a[2]), "r"(a[3]), "r"(b[0]), "r"(b[1]));
}

// ---------------- zero the gW/eW accumulators (graph-replay safe) ----------
__global__ void zero_kernel(float* a, float* b, float* c, float* d) {
    int i = blockIdx.x * 256 + threadIdx.x;
    if (i < KDIM) { a[i] = 0.f; b[i] = 0.f; }
    if (i < FDIM) { c[i] = 0.f; d[i] = 0.f; }
}

// ---------------- pack + fused gemv ----------------------------------------
// Wp[c][k] = fp16(g[k]*W[k][c]); also atomically accumulates
// gW[c] += sum_k g[k]W[k][c], eW[c] += sum_k lnb[k]W[k][c] (+bias[c] once).
__global__ void __launch_bounds__(256) pack_kernel(const float* __restrict__ W,
    const float* __restrict__ g, const float* __restrict__ lnb,
    const float* __restrict__ bias,
    __half* __restrict__ Wp, float* __restrict__ gW, float* __restrict__ eW, int C) {
    __shared__ float tg[32][33];   // g*W
    __shared__ float tb[32][33];   // lnb*W
    const int tx = threadIdx.x & 31;
    const int ty = threadIdx.x >> 5;          // 0..7
    const int c0 = blockIdx.x * 32;
    const int k0 = blockIdx.y * 32;
#pragma unroll
    for (int i = 0; i < 4; i++) {
        int k = k0 + ty + i * 8;
        float w = W[(size_t)k * C + c0 + tx];
        tg[ty + i * 8][tx] = g[k] * w;
        tb[ty + i * 8][tx] = lnb[k] * w;
    }
    __syncthreads();
#pragma unroll
    for (int i = 0; i < 4; i++) {
        int c = c0 + ty + i * 8;
        Wp[(size_t)c * KDIM + k0 + tx] = __float2half(tg[tx][ty + i * 8]);
        // reduce over k (lane index tx) for this column c
        float sg = tg[tx][ty + i * 8];
        float sb = tb[tx][ty + i * 8];
#pragma unroll
        for (int o = 16; o > 0; o >>= 1) {
            sg += __shfl_xor_sync(0xffffffffu, sg, o);
            sb += __shfl_xor_sync(0xffffffffu, sb, o);
        }
        if (tx == 0) {
            if (blockIdx.y == 0) sb += bias[c];
            atomicAdd(&gW[c], sg);
            atomicAdd(&eW[c], sb);
        }
    }
}

// ---------------- stage 1: LN1 stats + fp16 round, one warp per row --------
__global__ void __launch_bounds__(256) s1_kernel(
    const float* __restrict__ nodes, const float* __restrict__ aggr,
    const int* __restrict__ comps,
    __half* __restrict__ Aout, float* __restrict__ mu1, float* __restrict__ rs1,
    float* __restrict__ rsum, float* __restrict__ rsq, int n) {
    const int lane = threadIdx.x & 31;
    const int row  = blockIdx.x * 8 + (threadIdx.x >> 5);
    if (row >= n) return;
    const float4* p0 = (const float4*)(nodes + (size_t)row * FDIM);
    const float4* p1 = (const float4*)(aggr + (size_t)comps[row] * FDIM);
    float4 v0[4], v1[4];
#pragma unroll
    for (int i = 0; i < 4; i++) { v0[i] = p0[lane + 32 * i]; v1[i] = p1[lane + 32 * i]; }
    float s = 0.f, q = 0.f;
#pragma unroll
    for (int i = 0; i < 4; i++) {
        s += v0[i].x + v0[i].y + v0[i].z + v0[i].w + v1[i].x + v1[i].y + v1[i].z + v1[i].w;
        q += v0[i].x * v0[i].x + v0[i].y * v0[i].y + v0[i].z * v0[i].z + v0[i].w * v0[i].w
           + v1[i].x * v1[i].x + v1[i].y * v1[i].y + v1[i].z * v1[i].z + v1[i].w * v1[i].w;
    }
#pragma unroll
    for (int o = 16; o > 0; o >>= 1) {
        s += __shfl_xor_sync(0xffffffffu, s, o);
        q += __shfl_xor_sync(0xffffffffu, q, o);
    }
    if (lane == 0) {
        float mu = s * (1.0f / 1024.0f);
        float var = q * (1.0f / 1024.0f) - mu * mu;
        mu1[row] = mu; rs1[row] = rsqrtf(var + 1e-5f);
        rsum[row] = 0.f; rsq[row] = 0.f;
    }
    __half2* base = (__half2*)(Aout + (size_t)row * 1024);
#pragma unroll
    for (int i = 0; i < 4; i++) {
        int f = lane + 32 * i;
        base[2 * f + 0]       = __floats2half2_rn(v0[i].x, v0[i].y);
        base[2 * f + 1]       = __floats2half2_rn(v0[i].z, v0[i].w);
        base[256 + 2 * f + 0] = __floats2half2_rn(v1[i].x, v1[i].y);
        base[256 + 2 * f + 1] = __floats2half2_rn(v1[i].z, v1[i].w);
    }
}

// ---------------- HMMA GEMM: 1-term, warp 32x64, 3 stages ------------------
// LAYER==1: mu/rs are precomputed LN1 stats; epilogue -> silu -> H (fp16) +
//           LN2 partial sums (atomics into rsum/rsq).
// LAYER==2: mu/rs pointers carry rsum/rsq; epilogue computes LN2 stats inline,
//           then silu -> out (fp32).
template <int LAYER>
__global__ void __launch_bounds__(256, 2) gemm_kernel(
    const __half* __restrict__ Ain, const __half* __restrict__ Bp,
    const float* __restrict__ mu, const float* __restrict__ rs,
    const float* __restrict__ gW, const float* __restrict__ eW,
    __half* __restrict__ Hout, float* __restrict__ outp,
    float* __restrict__ rsum, float* __restrict__ rsq, int n, int ncols)
{
    extern __shared__ char smem[];
    uint32_t sb = smem_u32(smem);
    const int tid  = threadIdx.x;
    const int wid  = tid >> 5;
    const int lane = tid & 31;
    const int wm = wid & 3, wn = wid >> 2;
    const int row0 = blockIdx.y * BM;
    const int col0 = blockIdx.x * BN;

    float acc[2][8][4];
#pragma unroll
    for (int mt = 0; mt < 2; mt++)
#pragma unroll
        for (int nt = 0; nt < 8; nt++)
#pragma unroll
            for (int i = 0; i < 4; i++) acc[mt][nt][i] = 0.f;

    auto load_chunk = [&](int c) {
        int st = c % 3;
        uint32_t abase = sb + st * G_STAGE;
        uint32_t bbase = abase + TILE_BYTES;
        int kcol = c << 6;
#pragma unroll
        for (int i = 0; i < 4; i++) {
            int v = tid + i * 256, r = v >> 3, cc = v & 7;
            int rg = row0 + r; if (rg >= n) rg = n - 1;
            cp16(abase + SWZ(r * 128 + cc * 16), Ain + (size_t)rg * 1024 + kcol + cc * 8);
        }
#pragma unroll
        for (int i = 0; i < 4; i++) {
            int v = tid + i * 256, r = v >> 3, cc = v & 7;
            cp16(bbase + SWZ(r * 128 + cc * 16), Bp + (size_t)(col0 + r) * KDIM + kcol + cc * 8);
        }
        asm volatile("cp.async.commit_group;" ::: "memory");
    };

    load_chunk(0);
    load_chunk(1);

    const int a_row = wm * 32 + (lane & 15);
    const int b_row = wn * 64 + (lane & 15);
    const int k8    = (lane >> 4) * 8;

    for (int c = 0; c < NCHUNK; c++) {
        if (c + 2 < NCHUNK) asm volatile("cp.async.wait_group 1;" ::: "memory");
        else                asm volatile("cp.async.wait_group 0;" ::: "memory");
        __syncthreads();
        // Top barrier also publishes compute-done for stage (c+2)%3 == (c-1)%3.
        if (c + 2 < NCHUNK) load_chunk(c + 2);

        uint32_t abase = sb + (c % 3) * G_STAGE;
        uint32_t bbase = abase + TILE_BYTES;
#pragma unroll
        for (int ks = 0; ks < 4; ks++) {
            uint32_t a[2][4], b[8][2];
#pragma unroll
            for (int mt = 0; mt < 2; mt++)
                ldsm4(a[mt], abase + SWZ((a_row + mt * 16) * 128 + (ks * 16 + k8) * 2));
#pragma unroll
            for (int nt16 = 0; nt16 < 4; nt16++) {
                uint32_t r[4];
                ldsm4(r, bbase + SWZ((b_row + nt16 * 16) * 128 + (ks * 16 + k8) * 2));
                b[2 * nt16 + 0][0] = r[0]; b[2 * nt16 + 0][1] = r[2];
                b[2 * nt16 + 1][0] = r[1]; b[2 * nt16 + 1][1] = r[3];
            }
#pragma unroll
            for (int mt = 0; mt < 2; mt++)
#pragma unroll
                for (int nt = 0; nt < 8; nt++)
                    mma16816(acc[mt][nt], a[mt], b[nt]);
        }
    }

    // ---- epilogue ----
    const int qid   = lane >> 2;
    const int qlane = lane & 3;

    float gwv[8][2], ewv[8][2];
#pragma unroll
    for (int nt = 0; nt < 8; nt++) {
        int colb = col0 + wn * 64 + nt * 8 + qlane * 2;
        gwv[nt][0] = __ldg(gW + colb); gwv[nt][1] = __ldg(gW + colb + 1);
        ewv[nt][0] = __ldg(eW + colb); ewv[nt][1] = __ldg(eW + colb + 1);
    }

#pragma unroll
    for (int mt = 0; mt < 2; mt++) {
#pragma unroll
        for (int half = 0; half < 2; half++) {
            int row = row0 + wm * 32 + mt * 16 + qid + half * 8;
            bool valid = row < n;
            int rc = valid ? row : 0;
            float m_mu, m_rs;
            if (LAYER == 1) {
                m_mu = mu[rc]; m_rs = rs[rc];
            } else {
                m_mu = mu[rc] * (1.0f / 1024.0f);
                float var = rs[rc] * (1.0f / 1024.0f) - m_mu * m_mu;
                m_rs = rsqrtf(var + 1e-5f);
            }
            float ssum = 0.f, sq = 0.f;
#pragma unroll
            for (int nt = 0; nt < 8; nt++) {
                float c0 = m_rs * (acc[mt][nt][half * 2 + 0] - m_mu * gwv[nt][0]) + ewv[nt][0];
                float c1 = m_rs * (acc[mt][nt][half * 2 + 1] - m_mu * gwv[nt][1]) + ewv[nt][1];
                float h0 = c0 / (1.f + __expf(-c0));
                float h1 = c1 / (1.f + __expf(-c1));
                int colb = col0 + wn * 64 + nt * 8 + qlane * 2;
                if (LAYER == 1) {
                    ssum += h0 + h1; sq += h0 * h0 + h1 * h1;
                    if (valid)
                        *(__half2*)(Hout + (size_t)row * 1024 + colb) = __floats2half2_rn(h0, h1);
                } else {
                    if (valid) {
                        float2 v; v.x = h0; v.y = h1;
                        *(float2*)(outp + (size_t)row * ncols + colb) = v;
                    }
                }
            }
            if (LAYER == 1) {
                ssum += __shfl_xor_sync(0xffffffffu, ssum, 1);
                ssum += __shfl_xor_sync(0xffffffffu, ssum, 2);
                sq   += __shfl_xor_sync(0xffffffffu, sq, 1);
                sq   += __shfl_xor_sync(0xffffffffu, sq, 2);
                if (qlane == 0 && valid) {
                    atomicAdd(&rsum[row], ssum);
                    atomicAdd(&rsq[row], sq);
                }
            }
        }
    }
}

// ---------------------------------------------------------------------------
extern "C" void kernel_launch(void* const* d_in, const int* in_sizes, int n_in,
                              void* d_out, int out_size) {
    const float* nodes      = (const float*)d_in[1];
    const int*   comps      = (const int*)  d_in[2];
    const float* aggr_nodes = (const float*)d_in[4];
    const float* ln1_g      = (const float*)d_in[6];
    const float* ln1_b      = (const float*)d_in[7];
    const float* W1         = (const float*)d_in[8];
    const float* b1         = (const float*)d_in[9];
    const float* ln2_g      = (const float*)d_in[10];
    const float* ln2_b      = (const float*)d_in[11];
    const float* W2         = (const float*)d_in[12];
    const float* b2         = (const float*)d_in[13];
    float*       out        = (float*)d_out;

    const int n = in_sizes[1] / FDIM;

    __half *A, *H, *W1p, *W2p;
    float *gW1, *eW1, *gW2, *eW2, *mu1, *rs1, *rsum, *rsq;
    cudaGetSymbolAddress((void**)&A,    g_A);
    cudaGetSymbolAddress((void**)&H,    g_H);
    cudaGetSymbolAddress((void**)&W1p,  g_W1p);
    cudaGetSymbolAddress((void**)&W2p,  g_W2p);
    cudaGetSymbolAddress((void**)&gW1,  g_gW1);
    cudaGetSymbolAddress((void**)&eW1,  g_eW1);
    cudaGetSymbolAddress((void**)&gW2,  g_gW2);
    cudaGetSymbolAddress((void**)&eW2,  g_eW2);
    cudaGetSymbolAddress((void**)&mu1,  g_mu1);
    cudaGetSymbolAddress((void**)&rs1,  g_rs1);
    cudaGetSymbolAddress((void**)&rsum, g_rsum);
    cudaGetSymbolAddress((void**)&rsq,  g_rsq);

    cudaFuncSetAttribute(gemm_kernel<1>, cudaFuncAttributeMaxDynamicSharedMemorySize, G_SMEM);
    cudaFuncSetAttribute(gemm_kernel<2>, cudaFuncAttributeMaxDynamicSharedMemorySize, G_SMEM);

    const int rtiles = (n + BM - 1) / BM;

    // precompute (deterministic up to fp atomic ordering; within tolerance)
    zero_kernel<<<4, 256>>>(gW1, eW1, gW2, eW2);
    pack_kernel<<<dim3(KDIM / 32, KDIM / 32), 256>>>(W1, ln1_g, ln1_b, b1, W1p, gW1, eW1, KDIM);
    pack_kernel<<<dim3(FDIM / 32, KDIM / 32), 256>>>(W2, ln2_g, ln2_b, b2, W2p, gW2, eW2, FDIM);

    // stage 1: LN1 stats + fp16 round of concat(x), one warp per row
    s1_kernel<<<(n + 7) / 8, 256>>>(nodes, aggr_nodes, comps, A, mu1, rs1, rsum, rsq, n);

    // GEMM1 (1-term): h (fp16) + LN2 partial sums
    gemm_kernel<1><<<dim3(KDIM / BN, rtiles), 256, G_SMEM>>>(
        A, W1p, mu1, rs1, gW1, eW1, H, nullptr, rsum, rsq, n, KDIM);

    // GEMM2 (1-term, LN2 stats inline from rsum/rsq) -> out
    gemm_kernel<2><<<dim3(FDIM / BN, rtiles), 256, G_SMEM>>>(
        H, W2p, rsum, rsq, gW2, eW2, nullptr, out, nullptr, nullptr, n, FDIM);
}